// round 9
// baseline (speedup 1.0000x reference)
#include <cuda_runtime.h>
#include <math.h>

#define BB     32
#define SS     256
#define ISZ    1024
#define OSZ    1024
#define N4     4096
#define EPSF   1e-5f
#define NBLK   128
#define NTHR   256
#define CHUNK  256                 // k-extent per staged chunk
#define NCH    4                   // 1024 / 256

typedef unsigned long long ull;

// Scratch (device globals -- no runtime allocation allowed)
__device__ float    g_xproj[BB * SS * N4];    // x @ W_x + b for all timesteps
__device__ float    g_h[BB * OSZ];            // hidden state (global, cross-block)
__device__ float    g_part[2][BB][NBLK];      // LN partial sums [stat][row][block]
__device__ volatile unsigned g_flags[NBLK * 32];  // per-block barrier flags, 128B apart

// ---------------------------------------------------------------------------
// Packed f32x2 helpers (FFMA2 -- exact fp32 x2 per instruction)
// ---------------------------------------------------------------------------
__device__ __forceinline__ ull ffma2(ull a, ull b, ull c) {
    ull d;
    asm("fma.rn.f32x2 %0, %1, %2, %3;" : "=l"(d) : "l"(a), "l"(b), "l"(c));
    return d;
}
__device__ __forceinline__ ull splat2(float f) {
    ull d;
    asm("mov.b64 %0, {%1, %1};" : "=l"(d) : "f"(f));
    return d;
}
__device__ __forceinline__ float2 unpack2(ull v) {
    float2 r;
    asm("mov.b64 {%0, %1}, %2;" : "=f"(r.x), "=f"(r.y) : "l"(v));
    return r;
}

// ---------------------------------------------------------------------------
// Init: h from init_hx (broadcast over batch) AND reset all barrier flags.
// MUST cover BB*OSZ = 32768 threads: h state persists across graph replays,
// and stale h (or stale flags) poisons the timed replays.
// ---------------------------------------------------------------------------
__global__ void init_state(const float* __restrict__ init_hx) {
    int j = blockIdx.x * blockDim.x + threadIdx.x;
    if (j < NBLK * 32) g_flags[j] = 0u;
    if (j < BB * OSZ) g_h[j] = init_hx[j & (OSZ - 1)];
}

// ---------------------------------------------------------------------------
// xproj[row, n] = b[n] + sum_k x[row, k] * W[k, n]
// FFMA2 packed along N, 8 cols/thread: each x splat feeds 4 FFMA2.
// Block (32,8): thread = 4 rows x 8 cols. Grid (16, 256).
// ---------------------------------------------------------------------------
__global__ void xproj_kernel(const float* __restrict__ x,
                             const float* __restrict__ W,
                             const float* __restrict__ bias) {
    const int tx = threadIdx.x, ty = threadIdx.y;
    const int col0 = (blockIdx.x * 32 + tx) * 8;
    const int row0 = blockIdx.y * 32 + ty * 4;

    ull acc2[4][4];
    #pragma unroll
    for (int r = 0; r < 4; r++)
        #pragma unroll
        for (int c = 0; c < 4; c++) acc2[r][c] = 0ull;

    const float* xp = x + (size_t)row0 * ISZ;

    #pragma unroll 2
    for (int k = 0; k < ISZ; k += 4) {
        ulonglong2 wa[4], wb[4];
        #pragma unroll
        for (int kk = 0; kk < 4; kk++) {
            wa[kk] = *(const ulonglong2*)(W + (size_t)(k + kk) * N4 + col0);
            wb[kk] = *(const ulonglong2*)(W + (size_t)(k + kk) * N4 + col0 + 4);
        }
        float4 xv[4];
        #pragma unroll
        for (int r = 0; r < 4; r++)
            xv[r] = __ldg((const float4*)(xp + (size_t)r * ISZ + k));

        #pragma unroll
        for (int kk = 0; kk < 4; kk++) {
            #pragma unroll
            for (int r = 0; r < 4; r++) {
                float xs = (kk == 0) ? xv[r].x : (kk == 1) ? xv[r].y
                         : (kk == 2) ? xv[r].z : xv[r].w;
                ull xd = splat2(xs);
                acc2[r][0] = ffma2(xd, wa[kk].x, acc2[r][0]);
                acc2[r][1] = ffma2(xd, wa[kk].y, acc2[r][1]);
                acc2[r][2] = ffma2(xd, wb[kk].x, acc2[r][2]);
                acc2[r][3] = ffma2(xd, wb[kk].y, acc2[r][3]);
            }
        }
    }

    float4 bv0 = *(const float4*)(bias + col0);
    float4 bv1 = *(const float4*)(bias + col0 + 4);
    #pragma unroll
    for (int r = 0; r < 4; r++) {
        float2 p0 = unpack2(acc2[r][0]);
        float2 p1 = unpack2(acc2[r][1]);
        float2 p2 = unpack2(acc2[r][2]);
        float2 p3 = unpack2(acc2[r][3]);
        float4 o0, o1;
        o0.x = p0.x + bv0.x;  o0.y = p0.y + bv0.y;
        o0.z = p1.x + bv0.z;  o0.w = p1.y + bv0.w;
        o1.x = p2.x + bv1.x;  o1.y = p2.y + bv1.y;
        o1.z = p3.x + bv1.z;  o1.w = p3.y + bv1.w;
        *(float4*)(g_xproj + (size_t)(row0 + r) * N4 + col0)     = o0;
        *(float4*)(g_xproj + (size_t)(row0 + r) * N4 + col0 + 4) = o1;
    }
}

// ---------------------------------------------------------------------------
// Distributed-flag grid barrier: each block stores its phase to its own
// 128B-padded slot (no atomic serialization); warp 0 lanes poll 4 flags each.
// All NBLK blocks co-resident (1 block/SM by smem) -- no deadlock.
// ---------------------------------------------------------------------------
__device__ __forceinline__ void gsync(unsigned phase) {
    __syncthreads();
    if (threadIdx.x == 0) {
        __threadfence();
        g_flags[blockIdx.x * 32] = phase;
    }
    if (threadIdx.x < 32) {
        #pragma unroll
        for (int o = 0; o < NBLK; o += 32)
            while (g_flags[(threadIdx.x + o) * 32] < phase) { }
        __threadfence();
    }
    __syncthreads();
}

// ---------------------------------------------------------------------------
// Persistent LSTM recurrence (proven R5/R6 structure, flag barrier).
// Block `blk` owns output cols {g*1024 + blk*8 + q}.
// Warp mapping: tx -> col, ty -> k-subrange [ty*32, ty*32+32) of each chunk,
// accumulating partials for ALL 32 batch rows (32 x f32x2 accumulators).
// ---------------------------------------------------------------------------
__global__ void __launch_bounds__(NTHR, 1)
lstm_persist(const float* __restrict__ W,
             const float* __restrict__ gamma,
             const float* __restrict__ beta,
             const float* __restrict__ init_cx,
             float* __restrict__ out) {
    extern __shared__ float smem[];
    float4* __restrict__ Wsf4 = (float4*)smem;               // [8192] float4
    float*  __restrict__ Hreg = smem + 32768;                // 64KB region
    float4* __restrict__ Hbuf = (float4*)Hreg;               // [2][2048] float4
    float*  __restrict__ Pred = Hreg;                        // overlay: [32][8][32]
    __shared__ float c_sm[BB * 8];

    const int tid = threadIdx.x;
    const int tx  = tid & 31, ty = tid >> 5;
    const int blk = blockIdx.x;
    const int g   = tx >> 3, q = tx & 7;
    const int gcol = g * OSZ + blk * 8 + q;
    const int b0  = ty * 4;

    // Preload W_h slice into float4 layout: smem[(k>>2)*128 + c*4 + (k&3)]
    for (int idx = tid; idx < ISZ * 32; idx += NTHR) {
        int k = idx >> 5, c = idx & 31;
        int col = (c >> 3) * OSZ + blk * 8 + (c & 7);
        smem[(k >> 2) * 128 + c * 4 + (k & 3)] = W[(size_t)(ISZ + k) * N4 + col];
    }
    if (tid < BB * 8)
        c_sm[tid] = init_cx[blk * 8 + (tid & 7)];

    const float gam = gamma[gcol];
    const float bet = beta[gcol];

    // Cooperative-load source indices (8 float4 per chunk per thread)
    int ld_r[8], ld_j[8];
    #pragma unroll
    for (int u = 0; u < 8; u++) {
        int i = u * NTHR + tid;
        ld_r[u] = i >> 6;
        ld_j[u] = i & 63;
    }
    __syncthreads();

    unsigned nsync = 0;

    // Prefetch xproj for t=0
    float px[4];
    #pragma unroll
    for (int r = 0; r < 4; r++)
        px[r] = __ldcg(&g_xproj[((size_t)(b0 + r) * SS + 0) * N4 + gcol]);

    for (int t = 0; t < SS; t++) {
        float cur[4];
        #pragma unroll
        for (int r = 0; r < 4; r++) cur[r] = px[r];
        if (t + 1 < SS) {
            #pragma unroll
            for (int r = 0; r < 4; r++)
                px[r] = __ldcg(&g_xproj[((size_t)(b0 + r) * SS + t + 1) * N4 + gcol]);
        }

        // ---- stage chunk 0 of h ----
        {
            float4 ld[8];
            #pragma unroll
            for (int u = 0; u < 8; u++)
                ld[u] = __ldcg((const float4*)(g_h + (size_t)ld_r[u] * OSZ + ld_j[u] * 4));
            #pragma unroll
            for (int u = 0; u < 8; u++)
                Hbuf[u * NTHR + tid] = ld[u];
        }
        __syncthreads();

        // ---- recurrent GEMM: warp ty covers k in [c*256+ty*32, +32) for
        //      all 32 rows; f32x2 accumulators, one per row ----
        ull acc2[32];
        #pragma unroll
        for (int r = 0; r < 32; r++) acc2[r] = 0ull;

        #pragma unroll 1
        for (int c = 0; c < NCH; c++) {
            float4 ldn[8];
            if (c < NCH - 1) {
                const int k0n = (c + 1) * CHUNK;
                #pragma unroll
                for (int u = 0; u < 8; u++)
                    ldn[u] = __ldcg((const float4*)(g_h + (size_t)ld_r[u] * OSZ + k0n + ld_j[u] * 4));
            }

            const float4* __restrict__ hb = Hbuf + (c & 1) * 2048;
            const ulonglong2* __restrict__ wp =
                (const ulonglong2*)Wsf4 + (size_t)(c * 64 + ty * 8) * 32 + tx;

            #pragma unroll 4
            for (int jj = 0; jj < 8; jj++) {
                ulonglong2 wv = wp[jj * 32];            // {w[k],w[k+1]},{w[k+2],w[k+3]}
                const ulonglong2* __restrict__ hj =
                    (const ulonglong2*)(hb + (ty * 8 + jj));
                #pragma unroll
                for (int r = 0; r < 32; r++) {
                    ulonglong2 hv = hj[r * 64];         // broadcast: h[r][k..k+3]
                    acc2[r] = ffma2(hv.x, wv.x, acc2[r]);
                    acc2[r] = ffma2(hv.y, wv.y, acc2[r]);
                }
            }

            if (c < NCH - 1) {
                float4* __restrict__ hn = Hbuf + ((c + 1) & 1) * 2048;
                #pragma unroll
                for (int u = 0; u < 8; u++)
                    hn[u * NTHR + tid] = ldn[u];
                __syncthreads();
            }
        }

        // ---- cross-warp k-reduction via SMEM overlay ----
        #pragma unroll
        for (int r = 0; r < 32; r++) {
            float2 a = unpack2(acc2[r]);
            Pred[(r * 8 + ty) * 32 + tx] = a.x + a.y;
        }
        __syncthreads();

        float acc[4];
        #pragma unroll
        for (int r = 0; r < 4; r++) {
            const int row = b0 + r;
            float sum = 0.f;
            #pragma unroll
            for (int w = 0; w < 8; w++)
                sum += Pred[(row * 8 + w) * 32 + tx];
            acc[r] = sum + cur[r];
        }

        // ---- LN partial sums over this block's 32 columns, per row ----
        float s[4], ss[4];
        #pragma unroll
        for (int r = 0; r < 4; r++) { s[r] = acc[r]; ss[r] = acc[r] * acc[r]; }
        #pragma unroll
        for (int o = 16; o > 0; o >>= 1) {
            #pragma unroll
            for (int r = 0; r < 4; r++) {
                s[r]  += __shfl_xor_sync(0xffffffffu, s[r],  o);
                ss[r] += __shfl_xor_sync(0xffffffffu, ss[r], o);
            }
        }
        if (tx == 0) {
            #pragma unroll
            for (int r = 0; r < 4; r++) {
                __stcg(&g_part[0][b0 + r][blk], s[r]);
                __stcg(&g_part[1][b0 + r][blk], ss[r]);
            }
        }

        gsync(++nsync);

        // ---- aggregate stats (deterministic): warp ty handles rows b0..b0+3 ----
        float mean[4], rstd[4];
        #pragma unroll
        for (int r = 0; r < 4; r++) {
            int row = b0 + r;
            float4 sv = __ldcg((const float4*)&g_part[0][row][tx * 4]);
            float4 qv = __ldcg((const float4*)&g_part[1][row][tx * 4]);
            float sl = (sv.x + sv.y) + (sv.z + sv.w);
            float ql = (qv.x + qv.y) + (qv.z + qv.w);
            #pragma unroll
            for (int o = 16; o > 0; o >>= 1) {
                sl += __shfl_xor_sync(0xffffffffu, sl, o);
                ql += __shfl_xor_sync(0xffffffffu, ql, o);
            }
            float m = sl * (1.0f / N4);
            mean[r] = m;
            rstd[r] = rsqrtf(ql * (1.0f / N4) - m * m + EPSF);
        }

        // ---- LN + gates. Gates of index i sit in lanes q, q+8, q+16, q+24 ----
        #pragma unroll
        for (int r = 0; r < 4; r++) {
            float v = (acc[r] - mean[r]) * rstd[r] * gam + bet;
            float a0 = __shfl_sync(0xffffffffu, v, q);        // ig
            float a1 = __shfl_sync(0xffffffffu, v, q + 8);    // fg
            float a2 = __shfl_sync(0xffffffffu, v, q + 16);   // hidden
            float a3 = __shfl_sync(0xffffffffu, v, q + 24);   // og
            if (g == 0) {
                int b = b0 + r;
                int i = blk * 8 + q;
                float si = 1.0f / (1.0f + expf(-a0));
                float sf = 1.0f / (1.0f + expf(-a1));
                float so = 1.0f / (1.0f + expf(-a3));
                float co = c_sm[b * 8 + q];
                float cn = sf * co + si * tanhf(a2);
                float h  = so * cn;
                c_sm[b * 8 + q] = cn;
                __stcg(&g_h[(size_t)b * OSZ + i], h);
                out[((size_t)b * SS + t) * OSZ + i] = h;
            }
        }

        gsync(++nsync);
    }
}

// ---------------------------------------------------------------------------
// Inputs (metadata order): x, W, b, gamma, beta, init_hx, init_cx
// ---------------------------------------------------------------------------
extern "C" void kernel_launch(void* const* d_in, const int* in_sizes, int n_in,
                              void* d_out, int out_size) {
    const float* x       = (const float*)d_in[0];
    const float* W       = (const float*)d_in[1];
    const float* bias    = (const float*)d_in[2];
    const float* gamma   = (const float*)d_in[3];
    const float* beta    = (const float*)d_in[4];
    const float* init_hx = (const float*)d_in[5];
    const float* init_cx = (const float*)d_in[6];
    float* out = (float*)d_out;

    // 128 blocks: must cover BB*OSZ = 32768 h elements AND the 4096 flags
    init_state<<<(BB * OSZ + 255) / 256, 256>>>(init_hx);

    dim3 blk(32, 8);
    xproj_kernel<<<dim3(16, 256), blk>>>(x, W, bias);

    cudaFuncSetAttribute(lstm_persist,
                         cudaFuncAttributeMaxDynamicSharedMemorySize, 196608);
    lstm_persist<<<NBLK, NTHR, 196608>>>(W, gamma, beta, init_cx, out);
}

// round 10
// speedup vs baseline: 1.1439x; 1.1439x over previous
#include <cuda_runtime.h>
#include <math.h>

#define BB     32
#define SS     256
#define ISZ    1024
#define OSZ    1024
#define N4     4096
#define EPSF   1e-5f
#define NBLK   128
#define NTHR   256
#define CHUNK  256                 // k-extent per staged chunk
#define NCH    4                   // 1024 / 256

typedef unsigned long long ull;

// Scratch (device globals -- no runtime allocation allowed)
__device__ float    g_xproj[BB * SS * N4];    // x @ W_x + b for all timesteps
__device__ float    g_h[BB * OSZ];            // hidden state (global, cross-block)
__device__ float    g_part[2][BB][NBLK];      // LN partial sums [stat][row][block]
__device__ unsigned g_bar;                    // grid barrier counter

// ---------------------------------------------------------------------------
// Packed f32x2 helpers (FFMA2 -- exact fp32 x2 per instruction)
// ---------------------------------------------------------------------------
__device__ __forceinline__ ull ffma2(ull a, ull b, ull c) {
    ull d;
    asm("fma.rn.f32x2 %0, %1, %2, %3;" : "=l"(d) : "l"(a), "l"(b), "l"(c));
    return d;
}
__device__ __forceinline__ ull splat2(float f) {
    ull d;
    asm("mov.b64 %0, {%1, %1};" : "=l"(d) : "f"(f));
    return d;
}
__device__ __forceinline__ float2 unpack2(ull v) {
    float2 r;
    asm("mov.b64 {%0, %1}, %2;" : "=f"(r.x), "=f"(r.y) : "l"(v));
    return r;
}

// ---------------------------------------------------------------------------
// Init: h from init_hx (broadcast over batch), reset barrier.
// MUST cover BB*OSZ = 32768 elements: h persists across graph replays.
// ---------------------------------------------------------------------------
__global__ void init_state(const float* __restrict__ init_hx) {
    int j = blockIdx.x * blockDim.x + threadIdx.x;
    if (j == 0) g_bar = 0;
    if (j < BB * OSZ) g_h[j] = init_hx[j & (OSZ - 1)];
}

// ---------------------------------------------------------------------------
// xproj[row, n] = b[n] + sum_k x[row, k] * W[k, n]
// FFMA2 packed along N, 8 cols/thread: each x splat feeds 4 FFMA2.
// Block (32,8): thread = 4 rows x 8 cols. Grid (16, 256).
// ---------------------------------------------------------------------------
__global__ void xproj_kernel(const float* __restrict__ x,
                             const float* __restrict__ W,
                             const float* __restrict__ bias) {
    const int tx = threadIdx.x, ty = threadIdx.y;
    const int col0 = (blockIdx.x * 32 + tx) * 8;
    const int row0 = blockIdx.y * 32 + ty * 4;

    ull acc2[4][4];
    #pragma unroll
    for (int r = 0; r < 4; r++)
        #pragma unroll
        for (int c = 0; c < 4; c++) acc2[r][c] = 0ull;

    const float* xp = x + (size_t)row0 * ISZ;

    #pragma unroll 2
    for (int k = 0; k < ISZ; k += 4) {
        ulonglong2 wa[4], wb[4];
        #pragma unroll
        for (int kk = 0; kk < 4; kk++) {
            wa[kk] = *(const ulonglong2*)(W + (size_t)(k + kk) * N4 + col0);
            wb[kk] = *(const ulonglong2*)(W + (size_t)(k + kk) * N4 + col0 + 4);
        }
        float4 xv[4];
        #pragma unroll
        for (int r = 0; r < 4; r++)
            xv[r] = __ldg((const float4*)(xp + (size_t)r * ISZ + k));

        #pragma unroll
        for (int kk = 0; kk < 4; kk++) {
            #pragma unroll
            for (int r = 0; r < 4; r++) {
                float xs = (kk == 0) ? xv[r].x : (kk == 1) ? xv[r].y
                         : (kk == 2) ? xv[r].z : xv[r].w;
                ull xd = splat2(xs);
                acc2[r][0] = ffma2(xd, wa[kk].x, acc2[r][0]);
                acc2[r][1] = ffma2(xd, wa[kk].y, acc2[r][1]);
                acc2[r][2] = ffma2(xd, wb[kk].x, acc2[r][2]);
                acc2[r][3] = ffma2(xd, wb[kk].y, acc2[r][3]);
            }
        }
    }

    float4 bv0 = *(const float4*)(bias + col0);
    float4 bv1 = *(const float4*)(bias + col0 + 4);
    #pragma unroll
    for (int r = 0; r < 4; r++) {
        float2 p0 = unpack2(acc2[r][0]);
        float2 p1 = unpack2(acc2[r][1]);
        float2 p2 = unpack2(acc2[r][2]);
        float2 p3 = unpack2(acc2[r][3]);
        float4 o0, o1;
        o0.x = p0.x + bv0.x;  o0.y = p0.y + bv0.y;
        o0.z = p1.x + bv0.z;  o0.w = p1.y + bv0.w;
        o1.x = p2.x + bv1.x;  o1.y = p2.y + bv1.y;
        o1.z = p3.x + bv1.z;  o1.w = p3.y + bv1.w;
        *(float4*)(g_xproj + (size_t)(row0 + r) * N4 + col0)     = o0;
        *(float4*)(g_xproj + (size_t)(row0 + r) * N4 + col0 + 4) = o1;
    }
}

// ---------------------------------------------------------------------------
// Software grid barrier -- atomic counter on ONE hot L2 line (measured
// fastest: single-address atomics serialize at ~0.85cyc/lane; distributed
// flags force 128 distinct L2-line observations and lose by ~2.5us/barrier)
// ---------------------------------------------------------------------------
__device__ __forceinline__ void gsync(unsigned target) {
    __syncthreads();
    if (threadIdx.x == 0) {
        __threadfence();
        atomicAdd(&g_bar, 1u);
        while (*(volatile unsigned*)&g_bar < target) { }
        __threadfence();
    }
    __syncthreads();
}

// ---------------------------------------------------------------------------
// Persistent LSTM recurrence (proven R5/R6 structure -- unchanged from the
// 6039us run).
// Block `blk` owns output cols {g*1024 + blk*8 + q}.
// Warp mapping: tx -> col, ty -> k-subrange [ty*32, ty*32+32) of each chunk,
// accumulating partials for ALL 32 batch rows (32 x f32x2 accumulators).
// ---------------------------------------------------------------------------
__global__ void __launch_bounds__(NTHR, 1)
lstm_persist(const float* __restrict__ W,
             const float* __restrict__ gamma,
             const float* __restrict__ beta,
             const float* __restrict__ init_cx,
             float* __restrict__ out) {
    extern __shared__ float smem[];
    float4* __restrict__ Wsf4 = (float4*)smem;               // [8192] float4
    float*  __restrict__ Hreg = smem + 32768;                // 64KB region
    float4* __restrict__ Hbuf = (float4*)Hreg;               // [2][2048] float4
    float*  __restrict__ Pred = Hreg;                        // overlay: [32][8][32]
    __shared__ float c_sm[BB * 8];

    const int tid = threadIdx.x;
    const int tx  = tid & 31, ty = tid >> 5;
    const int blk = blockIdx.x;
    const int g   = tx >> 3, q = tx & 7;
    const int gcol = g * OSZ + blk * 8 + q;
    const int b0  = ty * 4;

    // Preload W_h slice into float4 layout: smem[(k>>2)*128 + c*4 + (k&3)]
    for (int idx = tid; idx < ISZ * 32; idx += NTHR) {
        int k = idx >> 5, c = idx & 31;
        int col = (c >> 3) * OSZ + blk * 8 + (c & 7);
        smem[(k >> 2) * 128 + c * 4 + (k & 3)] = W[(size_t)(ISZ + k) * N4 + col];
    }
    if (tid < BB * 8)
        c_sm[tid] = init_cx[blk * 8 + (tid & 7)];

    const float gam = gamma[gcol];
    const float bet = beta[gcol];

    // Cooperative-load source indices (8 float4 per chunk per thread)
    int ld_r[8], ld_j[8];
    #pragma unroll
    for (int u = 0; u < 8; u++) {
        int i = u * NTHR + tid;
        ld_r[u] = i >> 6;
        ld_j[u] = i & 63;
    }
    __syncthreads();

    unsigned nsync = 0;

    // Prefetch xproj for t=0
    float px[4];
    #pragma unroll
    for (int r = 0; r < 4; r++)
        px[r] = __ldcg(&g_xproj[((size_t)(b0 + r) * SS + 0) * N4 + gcol]);

    for (int t = 0; t < SS; t++) {
        float cur[4];
        #pragma unroll
        for (int r = 0; r < 4; r++) cur[r] = px[r];
        if (t + 1 < SS) {
            #pragma unroll
            for (int r = 0; r < 4; r++)
                px[r] = __ldcg(&g_xproj[((size_t)(b0 + r) * SS + t + 1) * N4 + gcol]);
        }

        // ---- stage chunk 0 of h ----
        {
            float4 ld[8];
            #pragma unroll
            for (int u = 0; u < 8; u++)
                ld[u] = __ldcg((const float4*)(g_h + (size_t)ld_r[u] * OSZ + ld_j[u] * 4));
            #pragma unroll
            for (int u = 0; u < 8; u++)
                Hbuf[u * NTHR + tid] = ld[u];
        }
        __syncthreads();

        // ---- recurrent GEMM: warp ty covers k in [c*256+ty*32, +32) for
        //      all 32 rows; f32x2 accumulators, one per row ----
        ull acc2[32];
        #pragma unroll
        for (int r = 0; r < 32; r++) acc2[r] = 0ull;

        #pragma unroll 1
        for (int c = 0; c < NCH; c++) {
            float4 ldn[8];
            if (c < NCH - 1) {
                const int k0n = (c + 1) * CHUNK;
                #pragma unroll
                for (int u = 0; u < 8; u++)
                    ldn[u] = __ldcg((const float4*)(g_h + (size_t)ld_r[u] * OSZ + k0n + ld_j[u] * 4));
            }

            const float4* __restrict__ hb = Hbuf + (c & 1) * 2048;
            const ulonglong2* __restrict__ wp =
                (const ulonglong2*)Wsf4 + (size_t)(c * 64 + ty * 8) * 32 + tx;

            #pragma unroll 4
            for (int jj = 0; jj < 8; jj++) {
                ulonglong2 wv = wp[jj * 32];            // {w[k],w[k+1]},{w[k+2],w[k+3]}
                const ulonglong2* __restrict__ hj =
                    (const ulonglong2*)(hb + (ty * 8 + jj));
                #pragma unroll
                for (int r = 0; r < 32; r++) {
                    ulonglong2 hv = hj[r * 64];         // broadcast: h[r][k..k+3]
                    acc2[r] = ffma2(hv.x, wv.x, acc2[r]);
                    acc2[r] = ffma2(hv.y, wv.y, acc2[r]);
                }
            }

            if (c < NCH - 1) {
                float4* __restrict__ hn = Hbuf + ((c + 1) & 1) * 2048;
                #pragma unroll
                for (int u = 0; u < 8; u++)
                    hn[u * NTHR + tid] = ldn[u];
                __syncthreads();
            }
        }

        // ---- cross-warp k-reduction via SMEM overlay ----
        #pragma unroll
        for (int r = 0; r < 32; r++) {
            float2 a = unpack2(acc2[r]);
            Pred[(r * 8 + ty) * 32 + tx] = a.x + a.y;
        }
        __syncthreads();

        float acc[4];
        #pragma unroll
        for (int r = 0; r < 4; r++) {
            const int row = b0 + r;
            float sum = 0.f;
            #pragma unroll
            for (int w = 0; w < 8; w++)
                sum += Pred[(row * 8 + w) * 32 + tx];
            acc[r] = sum + cur[r];
        }

        // ---- LN partial sums over this block's 32 columns, per row ----
        float s[4], ss[4];
        #pragma unroll
        for (int r = 0; r < 4; r++) { s[r] = acc[r]; ss[r] = acc[r] * acc[r]; }
        #pragma unroll
        for (int o = 16; o > 0; o >>= 1) {
            #pragma unroll
            for (int r = 0; r < 4; r++) {
                s[r]  += __shfl_xor_sync(0xffffffffu, s[r],  o);
                ss[r] += __shfl_xor_sync(0xffffffffu, ss[r], o);
            }
        }
        if (tx == 0) {
            #pragma unroll
            for (int r = 0; r < 4; r++) {
                __stcg(&g_part[0][b0 + r][blk], s[r]);
                __stcg(&g_part[1][b0 + r][blk], ss[r]);
            }
        }

        gsync(++nsync * NBLK);

        // ---- aggregate stats (deterministic): warp ty handles rows b0..b0+3 ----
        float mean[4], rstd[4];
        #pragma unroll
        for (int r = 0; r < 4; r++) {
            int row = b0 + r;
            float4 sv = __ldcg((const float4*)&g_part[0][row][tx * 4]);
            float4 qv = __ldcg((const float4*)&g_part[1][row][tx * 4]);
            float sl = (sv.x + sv.y) + (sv.z + sv.w);
            float ql = (qv.x + qv.y) + (qv.z + qv.w);
            #pragma unroll
            for (int o = 16; o > 0; o >>= 1) {
                sl += __shfl_xor_sync(0xffffffffu, sl, o);
                ql += __shfl_xor_sync(0xffffffffu, ql, o);
            }
            float m = sl * (1.0f / N4);
            mean[r] = m;
            rstd[r] = rsqrtf(ql * (1.0f / N4) - m * m + EPSF);
        }

        // ---- LN + gates. Gates of index i sit in lanes q, q+8, q+16, q+24 ----
        #pragma unroll
        for (int r = 0; r < 4; r++) {
            float v = (acc[r] - mean[r]) * rstd[r] * gam + bet;
            float a0 = __shfl_sync(0xffffffffu, v, q);        // ig
            float a1 = __shfl_sync(0xffffffffu, v, q + 8);    // fg
            float a2 = __shfl_sync(0xffffffffu, v, q + 16);   // hidden
            float a3 = __shfl_sync(0xffffffffu, v, q + 24);   // og
            if (g == 0) {
                int b = b0 + r;
                int i = blk * 8 + q;
                float si = 1.0f / (1.0f + expf(-a0));
                float sf = 1.0f / (1.0f + expf(-a1));
                float so = 1.0f / (1.0f + expf(-a3));
                float co = c_sm[b * 8 + q];
                float cn = sf * co + si * tanhf(a2);
                float h  = so * cn;
                c_sm[b * 8 + q] = cn;
                __stcg(&g_h[(size_t)b * OSZ + i], h);
                out[((size_t)b * SS + t) * OSZ + i] = h;
            }
        }

        gsync(++nsync * NBLK);
    }
}

// ---------------------------------------------------------------------------
// Inputs (metadata order): x, W, b, gamma, beta, init_hx, init_cx
// ---------------------------------------------------------------------------
extern "C" void kernel_launch(void* const* d_in, const int* in_sizes, int n_in,
                              void* d_out, int out_size) {
    const float* x       = (const float*)d_in[0];
    const float* W       = (const float*)d_in[1];
    const float* bias    = (const float*)d_in[2];
    const float* gamma   = (const float*)d_in[3];
    const float* beta    = (const float*)d_in[4];
    const float* init_hx = (const float*)d_in[5];
    const float* init_cx = (const float*)d_in[6];
    float* out = (float*)d_out;

    // 128 blocks: must cover BB*OSZ = 32768 h elements
    init_state<<<(BB * OSZ + 255) / 256, 256>>>(init_hx);

    dim3 blk(32, 8);
    xproj_kernel<<<dim3(16, 256), blk>>>(x, W, bias);

    cudaFuncSetAttribute(lstm_persist,
                         cudaFuncAttributeMaxDynamicSharedMemorySize, 196608);
    lstm_persist<<<NBLK, NTHR, 196608>>>(W, gamma, beta, init_cx, out);
}